// round 10
// baseline (speedup 1.0000x reference)
#include <cuda_runtime.h>

#define NNODES 100000
#define NEDGES 1250000
#define NGRAPH 256
#define H      64
#define NCLS   10

// ---- scratch (static device globals; no allocation) ----
__device__ float g_bufA[NNODES * H];     // transformed features h = in @ W
__device__ float g_bufB[NNODES * H];     // scatter accumulator
__device__ float g_degf[NNODES];
__device__ float g_dinv[NNODES];
__device__ int   g_esrc[NEDGES];         // compact edge list (built once per call)
__device__ int   g_edst[NEDGES];
__device__ float g_enrm[NEDGES];
__device__ float g_pool[NGRAPH * H];
__device__ float g_cnt[NGRAPH];

__device__ __forceinline__ void red_add_v4(float* p, float4 v) {
    asm volatile("red.global.add.v4.f32 [%0], {%1,%2,%3,%4};"
                 :: "l"(p), "f"(v.x), "f"(v.y), "f"(v.z), "f"(v.w)
                 : "memory");
}

// ---- init: deg=1 (self loop), pool/cnt = 0 ----
__global__ void __launch_bounds__(256) k_init(int n) {
    int i = blockIdx.x * blockDim.x + threadIdx.x;
    if (i < n)           g_degf[i] = 1.0f;
    if (i < NGRAPH * H)  g_pool[i] = 0.0f;
    if (i < NGRAPH)      g_cnt[i]  = 0.0f;
}

// ---- degree count over dst (indices are int32: JAX default x64-disabled) ----
__global__ void __launch_bounds__(256) k_deg(const int* __restrict__ ei, int ne, int n) {
    int e = blockIdx.x * blockDim.x + threadIdx.x;
    if (e >= ne) return;
    int s = ei[e];
    int d = ei[ne + e];
    g_esrc[e] = s;
    g_edst[e] = d;
    if ((unsigned)d < (unsigned)n) atomicAdd(&g_degf[d], 1.0f);
}

__global__ void __launch_bounds__(256) k_dinv(int n) {
    int i = blockIdx.x * blockDim.x + threadIdx.x;
    if (i < n) g_dinv[i] = rsqrtf(g_degf[i]);
}

// ---- per-edge norm, computed once, reused by all 3 layers ----
__global__ void __launch_bounds__(256) k_enorm(int ne, int n) {
    int e = blockIdx.x * blockDim.x + threadIdx.x;
    if (e >= ne) return;
    int s = g_esrc[e];
    int d = g_edst[e];
    float v = 0.0f;
    if ((unsigned)s < (unsigned)n && (unsigned)d < (unsigned)n)
        v = g_dinv[s] * g_dinv[d];
    g_enrm[e] = v;
}

// ---- GEMM + fused self-loop epilogue ----
// out[r,:] = act(in[r,:] (+bias, relu)) @ W            (h)
// acc[r,:] = dinv[r]^2 * out[r,:]                      (scatter accumulator init)
// Safe when acc == in: each block reads only its own 16 rows (before
// __syncthreads) and writes only those same rows (after).
__global__ void __launch_bounds__(256) k_gemm(
        const float* __restrict__ in, const float* __restrict__ W,
        const float* __restrict__ bias, int relu,
        float* __restrict__ out, float* __restrict__ acc, int n) {
    __shared__ float sW[64 * 64];
    __shared__ float sIn[16][64];
    int t = threadIdx.x;                // 256 threads
    #pragma unroll
    for (int i = 0; i < 16; i++) sW[t + i * 256] = W[t + i * 256];
    int row0 = blockIdx.x * 16;
    {
        // one float4 per thread: 16 rows x 16 float4
        int r  = t >> 4;
        int c4 = t & 15;
        int gr = row0 + r;
        float4 v = make_float4(0.f, 0.f, 0.f, 0.f);
        if (gr < n) {
            v = reinterpret_cast<const float4*>(in)[gr * 16 + c4];
            if (bias) {
                float4 b = reinterpret_cast<const float4*>(bias)[c4];
                v.x += b.x; v.y += b.y; v.z += b.z; v.w += b.w;
                if (relu) {
                    v.x = fmaxf(v.x, 0.f); v.y = fmaxf(v.y, 0.f);
                    v.z = fmaxf(v.z, 0.f); v.w = fmaxf(v.w, 0.f);
                }
            }
        }
        sIn[r][c4 * 4 + 0] = v.x;
        sIn[r][c4 * 4 + 1] = v.y;
        sIn[r][c4 * 4 + 2] = v.z;
        sIn[r][c4 * 4 + 3] = v.w;
    }
    __syncthreads();
    int col = t & 63;
    int rb  = t >> 6;                   // 0..3
    float a0 = 0.f, a1 = 0.f, a2 = 0.f, a3 = 0.f;
    #pragma unroll
    for (int k = 0; k < 64; k++) {
        float w = sW[k * 64 + col];
        a0 += sIn[rb     ][k] * w;
        a1 += sIn[rb +  4][k] * w;
        a2 += sIn[rb +  8][k] * w;
        a3 += sIn[rb + 12][k] * w;
    }
    #pragma unroll
    for (int i = 0; i < 4; i++) {
        int gr = row0 + rb + i * 4;
        float a = (i == 0) ? a0 : (i == 1) ? a1 : (i == 2) ? a2 : a3;
        if (gr < n) {
            out[gr * 64 + col] = a;
            float d = g_dinv[gr];
            acc[gr * 64 + col] = d * d * a;
        }
    }
}

// ---- edge scatter: 8 threads/edge, 2x red.v4 each ----
__global__ void __launch_bounds__(256) k_scatter(int ne, int n) {
    long long tid = (long long)blockIdx.x * blockDim.x + threadIdx.x;
    int e = (int)(tid >> 3);
    if (e >= ne) return;
    int part = (int)(tid & 7);
    int   src = __ldg(&g_esrc[e]);
    int   dst = __ldg(&g_edst[e]);
    float nrm = __ldg(&g_enrm[e]);
    if ((unsigned)src >= (unsigned)n || (unsigned)dst >= (unsigned)n) return;
    const float4* hs = reinterpret_cast<const float4*>(g_bufA + src * 64) + part * 2;
    float4 v0 = __ldg(hs);
    float4 v1 = __ldg(hs + 1);
    v0.x *= nrm; v0.y *= nrm; v0.z *= nrm; v0.w *= nrm;
    v1.x *= nrm; v1.y *= nrm; v1.z *= nrm; v1.w *= nrm;
    float* ap = g_bufB + dst * 64 + part * 8;
    red_add_v4(ap,     v0);
    red_add_v4(ap + 4, v1);
}

// ---- pool: per node, +b3, red.v4 into graph sums ----
__global__ void __launch_bounds__(256) k_pool(
        const int* __restrict__ batch,
        const float* __restrict__ b3, int n) {
    long long tid = (long long)blockIdx.x * blockDim.x + threadIdx.x;
    int node = (int)(tid >> 4);
    if (node >= n) return;
    int part = (int)(tid & 15);
    int g = batch[node];
    if ((unsigned)g >= (unsigned)NGRAPH) return;
    float4 v = reinterpret_cast<const float4*>(g_bufB + node * 64)[part];
    float4 b = reinterpret_cast<const float4*>(b3)[part];
    v.x += b.x; v.y += b.y; v.z += b.z; v.w += b.w;
    red_add_v4(g_pool + g * 64 + part * 4, v);
    if (part == 0) atomicAdd(&g_cnt[g], 1.0f);
}

// ---- final linear: out[g, c] = (pool[g]/max(cnt,1)) @ Wlin + blin ----
__global__ void __launch_bounds__(64) k_final(
        const float* __restrict__ Wlin,
        const float* __restrict__ blin,
        float* __restrict__ out) {
    __shared__ float sp[64];
    int g = blockIdx.x;
    int t = threadIdx.x;                // 64
    float inv = 1.0f / fmaxf(g_cnt[g], 1.0f);
    sp[t] = g_pool[g * 64 + t] * inv;
    __syncthreads();
    if (t < NCLS) {
        float s = blin[t];
        #pragma unroll
        for (int k = 0; k < 64; k++) s += sp[k] * Wlin[k * NCLS + t];
        out[g * NCLS + t] = s;
    }
}

extern "C" void kernel_launch(void* const* d_in, const int* in_sizes, int n_in,
                              void* d_out, int out_size) {
    const float* x     = (const float*)d_in[0];
    const int*   ei    = (const int*)d_in[1];     // int32 (JAX x64 disabled)
    const int*   batch = (const int*)d_in[2];     // int32
    const float* W1    = (const float*)d_in[3];
    const float* b1    = (const float*)d_in[4];
    const float* W2    = (const float*)d_in[5];
    const float* b2    = (const float*)d_in[6];
    const float* W3    = (const float*)d_in[7];
    const float* b3    = (const float*)d_in[8];
    const float* Wlin  = (const float*)d_in[9];
    const float* blin  = (const float*)d_in[10];
    float* out = (float*)d_out;

    int n  = in_sizes[0] / H;     // 100000
    int ne = in_sizes[1] / 2;     // 1250000

    float* bufA; cudaGetSymbolAddress((void**)&bufA, g_bufA);
    float* bufB; cudaGetSymbolAddress((void**)&bufB, g_bufB);

    const int T = 256;
    int nb_n  = (n + T - 1) / T;
    int nb_e  = (ne + T - 1) / T;
    long long sth = (long long)ne * 8;
    int nb_s  = (int)((sth + T - 1) / T);
    int nb_g  = (n + 15) / 16;

    k_init  <<<nb_n, T>>>(n);
    k_deg   <<<nb_e, T>>>(ei, ne, n);
    k_dinv  <<<nb_n, T>>>(n);
    k_enorm <<<nb_e, T>>>(ne, n);

    // layer 1: h1 -> bufA, acc init -> bufB, then scatter into bufB
    k_gemm   <<<nb_g, 256>>>(x,    W1, nullptr, 0, bufA, bufB, n);
    k_scatter<<<nb_s, T>>>(ne, n);
    // layer 2 (fold b1 + relu into input read; bufB is both in and acc)
    k_gemm   <<<nb_g, 256>>>(bufB, W2, b1, 1, bufA, bufB, n);
    k_scatter<<<nb_s, T>>>(ne, n);
    // layer 3 (fold b2 + relu into input read)
    k_gemm   <<<nb_g, 256>>>(bufB, W3, b2, 1, bufA, bufB, n);
    k_scatter<<<nb_s, T>>>(ne, n);

    // pool (+b3) and classify
    long long pth = (long long)n * 16;
    k_pool <<<(int)((pth + T - 1) / T), T>>>(batch, b3, n);
    k_final<<<NGRAPH, 64>>>(Wlin, blin, out);
}

// round 11
// speedup vs baseline: 2.2507x; 2.2507x over previous
#include <cuda_runtime.h>

#define NNODES 100000
#define NEDGES 1250000
#define NGRAPH 256
#define H      64
#define NCLS   10
#define MAXBLK 512

// ---- scratch (static device globals; no allocation) ----
__device__ float g_bufA[NNODES * H];   // h = in @ W
__device__ float g_bufB[NNODES * H];   // aggregated output per layer
__device__ int   g_degi[NNODES];       // in-degree (excluding self loop)
__device__ float g_dinv[NNODES];
__device__ int   g_esrc[NEDGES];       // narrowed edge list
__device__ int   g_edst[NEDGES];
__device__ int   g_rowptr[NNODES];     // CSR row starts (by dst)
__device__ int   g_cursor[NNODES];     // fill cursors
__device__ int   g_csrc[NEDGES];       // CSR: src per slot
__device__ float g_cnrm[NEDGES];       // CSR: norm per slot
__device__ int   g_bsum[MAXBLK];
__device__ int   g_boff[MAXBLK];
__device__ float g_pool[NGRAPH * H];
__device__ float g_cnt[NGRAPH];

__device__ __forceinline__ void red_add_v4(float* p, float4 v) {
    asm volatile("red.global.add.v4.f32 [%0], {%1,%2,%3,%4};"
                 :: "l"(p), "f"(v.x), "f"(v.y), "f"(v.z), "f"(v.w)
                 : "memory");
}

// ---- init ----
__global__ void __launch_bounds__(256) k_init(int n) {
    int i = blockIdx.x * blockDim.x + threadIdx.x;
    if (i < n)           g_degi[i] = 0;
    if (i < NGRAPH * H)  g_pool[i] = 0.0f;
    if (i < NGRAPH)      g_cnt[i]  = 0.0f;
}

// ---- narrow indices + in-degree histogram ----
__global__ void __launch_bounds__(256) k_deg(const int* __restrict__ ei, int ne, int n) {
    int e = blockIdx.x * blockDim.x + threadIdx.x;
    if (e >= ne) return;
    int s = ei[e];
    int d = ei[ne + e];
    g_esrc[e] = s;
    g_edst[e] = d;
    if ((unsigned)d < (unsigned)n) atomicAdd(&g_degi[d], 1);
}

// ---- block-wise exclusive scan of degi (step 1) ----
__global__ void __launch_bounds__(256) k_scan1(int n) {
    __shared__ int sh[256];
    int tid = threadIdx.x;
    int i = blockIdx.x * 256 + tid;
    int v = (i < n) ? g_degi[i] : 0;
    sh[tid] = v;
    __syncthreads();
    #pragma unroll
    for (int off = 1; off < 256; off <<= 1) {
        int t = (tid >= off) ? sh[tid - off] : 0;
        __syncthreads();
        sh[tid] += t;
        __syncthreads();
    }
    if (i < n) g_rowptr[i] = sh[tid] - v;     // exclusive within block
    if (tid == 255) g_bsum[blockIdx.x] = sh[255];
}

// ---- scan of block sums (step 2), single block ----
__global__ void __launch_bounds__(MAXBLK) k_scan2(int nb) {
    __shared__ int sh[MAXBLK];
    int t = threadIdx.x;
    int v = (t < nb) ? g_bsum[t] : 0;
    sh[t] = v;
    __syncthreads();
    #pragma unroll
    for (int off = 1; off < MAXBLK; off <<= 1) {
        int u = (t >= off) ? sh[t - off] : 0;
        __syncthreads();
        sh[t] += u;
        __syncthreads();
    }
    if (t < nb) g_boff[t] = sh[t] - v;        // exclusive block offsets
}

// ---- add block offsets, init cursors, compute dinv (step 3) ----
__global__ void __launch_bounds__(256) k_scan3(int n) {
    int i = blockIdx.x * blockDim.x + threadIdx.x;
    if (i >= n) return;
    int rp = g_rowptr[i] + g_boff[i >> 8];
    g_rowptr[i] = rp;
    g_cursor[i] = rp;
    g_dinv[i]   = rsqrtf(1.0f + (float)g_degi[i]);  // +1 self loop
}

// ---- fill CSR slots (order within node irrelevant) ----
__global__ void __launch_bounds__(256) k_fill(int ne, int n) {
    int e = blockIdx.x * blockDim.x + threadIdx.x;
    if (e >= ne) return;
    int s = g_esrc[e];
    int d = g_edst[e];
    if ((unsigned)d >= (unsigned)n) return;
    int slot = atomicAdd(&g_cursor[d], 1);
    float nrm = 0.0f;
    int   ss  = 0;
    if ((unsigned)s < (unsigned)n) { nrm = g_dinv[s] * g_dinv[d]; ss = s; }
    g_csrc[slot] = ss;
    g_cnrm[slot] = nrm;
}

// ---- GEMM: out[r,:] = act(in[r,:] (+bias, relu)) @ W ; 16 rows/block ----
__global__ void __launch_bounds__(256) k_gemm(
        const float* __restrict__ in, const float* __restrict__ W,
        const float* __restrict__ bias, int relu,
        float* __restrict__ out, int n) {
    __shared__ float sW[64 * 64];
    __shared__ float sIn[16][64];
    int t = threadIdx.x;                // 256 threads
    #pragma unroll
    for (int i = 0; i < 16; i++) sW[t + i * 256] = W[t + i * 256];
    int row0 = blockIdx.x * 16;
    {
        int r  = t >> 4;
        int c4 = t & 15;
        int gr = row0 + r;
        float4 v = make_float4(0.f, 0.f, 0.f, 0.f);
        if (gr < n) {
            v = reinterpret_cast<const float4*>(in)[gr * 16 + c4];
            if (bias) {
                float4 b = reinterpret_cast<const float4*>(bias)[c4];
                v.x += b.x; v.y += b.y; v.z += b.z; v.w += b.w;
                if (relu) {
                    v.x = fmaxf(v.x, 0.f); v.y = fmaxf(v.y, 0.f);
                    v.z = fmaxf(v.z, 0.f); v.w = fmaxf(v.w, 0.f);
                }
            }
        }
        sIn[r][c4 * 4 + 0] = v.x;
        sIn[r][c4 * 4 + 1] = v.y;
        sIn[r][c4 * 4 + 2] = v.z;
        sIn[r][c4 * 4 + 3] = v.w;
    }
    __syncthreads();
    int col = t & 63;
    int rb  = t >> 6;                   // 0..3
    float a0 = 0.f, a1 = 0.f, a2 = 0.f, a3 = 0.f;
    #pragma unroll
    for (int k = 0; k < 64; k++) {
        float w = sW[k * 64 + col];
        a0 += sIn[rb     ][k] * w;
        a1 += sIn[rb +  4][k] * w;
        a2 += sIn[rb +  8][k] * w;
        a3 += sIn[rb + 12][k] * w;
    }
    if (row0 + rb      < n) out[(row0 + rb     ) * 64 + col] = a0;
    if (row0 + rb +  4 < n) out[(row0 + rb +  4) * 64 + col] = a1;
    if (row0 + rb +  8 < n) out[(row0 + rb +  8) * 64 + col] = a2;
    if (row0 + rb + 12 < n) out[(row0 + rb + 12) * 64 + col] = a3;
}

// ---- gather: one warp per node; bufB = dinv^2*bufA[node] + sum(nrm*bufA[src]) ----
__global__ void __launch_bounds__(256) k_gather(int n) {
    int gt   = blockIdx.x * 256 + threadIdx.x;
    int node = gt >> 5;
    if (node >= n) return;
    int lane = threadIdx.x & 31;
    int beg = g_rowptr[node];
    int end = beg + g_degi[node];
    float d = g_dinv[node];
    float c = d * d;
    float2 s = reinterpret_cast<const float2*>(g_bufA + node * 64)[lane];
    float ax = c * s.x, ay = c * s.y;
    int i = beg;
    for (; i + 2 <= end; i += 2) {
        int   s0 = __ldg(&g_csrc[i]);
        int   s1 = __ldg(&g_csrc[i + 1]);
        float w0 = __ldg(&g_cnrm[i]);
        float w1 = __ldg(&g_cnrm[i + 1]);
        float2 v0 = __ldg(reinterpret_cast<const float2*>(g_bufA + s0 * 64) + lane);
        float2 v1 = __ldg(reinterpret_cast<const float2*>(g_bufA + s1 * 64) + lane);
        ax += w0 * v0.x + w1 * v1.x;
        ay += w0 * v0.y + w1 * v1.y;
    }
    if (i < end) {
        int   s0 = __ldg(&g_csrc[i]);
        float w0 = __ldg(&g_cnrm[i]);
        float2 v0 = __ldg(reinterpret_cast<const float2*>(g_bufA + s0 * 64) + lane);
        ax += w0 * v0.x;
        ay += w0 * v0.y;
    }
    reinterpret_cast<float2*>(g_bufB + node * 64)[lane] = make_float2(ax, ay);
}

// ---- pool: per node, +b3, red.v4 into graph sums ----
__global__ void __launch_bounds__(256) k_pool(
        const int* __restrict__ batch,
        const float* __restrict__ b3, int n) {
    long long tid = (long long)blockIdx.x * blockDim.x + threadIdx.x;
    int node = (int)(tid >> 4);
    if (node >= n) return;
    int part = (int)(tid & 15);
    int g = batch[node];
    if ((unsigned)g >= (unsigned)NGRAPH) return;
    float4 v = reinterpret_cast<const float4*>(g_bufB + node * 64)[part];
    float4 b = reinterpret_cast<const float4*>(b3)[part];
    v.x += b.x; v.y += b.y; v.z += b.z; v.w += b.w;
    red_add_v4(g_pool + g * 64 + part * 4, v);
    if (part == 0) atomicAdd(&g_cnt[g], 1.0f);
}

// ---- final linear ----
__global__ void __launch_bounds__(64) k_final(
        const float* __restrict__ Wlin,
        const float* __restrict__ blin,
        float* __restrict__ out) {
    __shared__ float sp[64];
    int g = blockIdx.x;
    int t = threadIdx.x;
    float inv = 1.0f / fmaxf(g_cnt[g], 1.0f);
    sp[t] = g_pool[g * 64 + t] * inv;
    __syncthreads();
    if (t < NCLS) {
        float s = blin[t];
        #pragma unroll
        for (int k = 0; k < 64; k++) s += sp[k] * Wlin[k * NCLS + t];
        out[g * NCLS + t] = s;
    }
}

extern "C" void kernel_launch(void* const* d_in, const int* in_sizes, int n_in,
                              void* d_out, int out_size) {
    const float* x     = (const float*)d_in[0];
    const int*   ei    = (const int*)d_in[1];     // int32 (JAX x64 disabled)
    const int*   batch = (const int*)d_in[2];     // int32
    const float* W1    = (const float*)d_in[3];
    const float* b1    = (const float*)d_in[4];
    const float* W2    = (const float*)d_in[5];
    const float* b2    = (const float*)d_in[6];
    const float* W3    = (const float*)d_in[7];
    const float* b3    = (const float*)d_in[8];
    const float* Wlin  = (const float*)d_in[9];
    const float* blin  = (const float*)d_in[10];
    float* out = (float*)d_out;

    int n  = in_sizes[0] / H;     // 100000
    int ne = in_sizes[1] / 2;     // 1250000

    float* bufA; cudaGetSymbolAddress((void**)&bufA, g_bufA);
    float* bufB; cudaGetSymbolAddress((void**)&bufB, g_bufB);

    const int T = 256;
    int nb_n    = (n + T - 1) / T;
    int nb_e    = (ne + T - 1) / T;
    int nb_g    = (n + 15) / 16;
    int nb_scan = (n + 255) / 256;                 // 391 <= MAXBLK
    int nb_gath = (n * 32 + T - 1) / T;            // one warp per node

    // ---- setup: degree, scan -> CSR rowptr, fill ----
    k_init <<<nb_n, T>>>(n);
    k_deg  <<<nb_e, T>>>(ei, ne, n);
    k_scan1<<<nb_scan, 256>>>(n);
    k_scan2<<<1, MAXBLK>>>(nb_scan);
    k_scan3<<<nb_n, T>>>(n);
    k_fill <<<nb_e, T>>>(ne, n);

    // ---- layer 1 ----
    k_gemm  <<<nb_g, 256>>>(x,    W1, nullptr, 0, bufA, n);
    k_gather<<<nb_gath, T>>>(n);
    // ---- layer 2 (fold b1 + relu into input read) ----
    k_gemm  <<<nb_g, 256>>>(bufB, W2, b1, 1, bufA, n);
    k_gather<<<nb_gath, T>>>(n);
    // ---- layer 3 (fold b2 + relu into input read) ----
    k_gemm  <<<nb_g, 256>>>(bufB, W3, b2, 1, bufA, n);
    k_gather<<<nb_gath, T>>>(n);

    // ---- pool (+b3) and classify ----
    long long pth = (long long)n * 16;
    k_pool <<<(int)((pth + T - 1) / T), T>>>(batch, b3, n);
    k_final<<<NGRAPH, 64>>>(Wlin, blin, out);
}